// round 3
// baseline (speedup 1.0000x reference)
#include <cuda_runtime.h>
#include <math.h>

#define BB 32
#define NN 1024
#define FF 128

// 128MB scratch: stores E = exp(current matrix) (in-place updated each half-step)
__device__ float g_E[BB * NN * NN];
__device__ float g_rowsum[BB * NN];
__device__ float g_colsum[BB * NN];

// ---------------------------------------------------------------------------
// Step 1: m = (template + gumbel)/T ; row softmax (with max); store E = exp(y1)
// One block per (b, row). 256 threads, 4 elems/thread.
// ---------------------------------------------------------------------------
__global__ __launch_bounds__(256) void k_init(const float* __restrict__ tmpl,
                                              const float* __restrict__ uni) {
    const int b = blockIdx.y, i = blockIdx.x, t = threadIdx.x;
    const size_t base = ((size_t)b * NN + i) * NN;
    const size_t tb = (size_t)i * NN;

    float x[4];
#pragma unroll
    for (int k = 0; k < 4; k++) {
        int j = t + k * 256;
        float u = uni[base + j];
        // accurate logf: relative error spec matters near u ~ 1 (tiny inner log)
        float g = -logf(-logf(u + 1e-12f) + 1e-12f);
        x[k] = (tmpl[tb + j] + g) * 5.0f;   // 1/0.2
    }

    __shared__ float red[8];

    // block max
    float mx = fmaxf(fmaxf(x[0], x[1]), fmaxf(x[2], x[3]));
#pragma unroll
    for (int o = 16; o > 0; o >>= 1) mx = fmaxf(mx, __shfl_xor_sync(0xffffffffu, mx, o));
    if ((t & 31) == 0) red[t >> 5] = mx;
    __syncthreads();
    if (t < 32) {
        float v = (t < 8) ? red[t] : -3.4e38f;
#pragma unroll
        for (int o = 4; o > 0; o >>= 1) v = fmaxf(v, __shfl_xor_sync(0xffffffffu, v, o));
        if (t == 0) red[0] = v;
    }
    __syncthreads();
    mx = red[0];
    __syncthreads();

    // exp + block sum
    float e[4], s = 0.f;
#pragma unroll
    for (int k = 0; k < 4; k++) { e[k] = expf(x[k] - mx); s += e[k]; }
#pragma unroll
    for (int o = 16; o > 0; o >>= 1) s += __shfl_xor_sync(0xffffffffu, s, o);
    if ((t & 31) == 0) red[t >> 5] = s;
    __syncthreads();
    if (t < 32) {
        float v = (t < 8) ? red[t] : 0.f;
#pragma unroll
        for (int o = 4; o > 0; o >>= 1) v += __shfl_xor_sync(0xffffffffu, v, o);
        if (t == 0) red[0] = v;
    }
    __syncthreads();
    const float inv = 1.0f / red[0];

    // store E = exp(row-softmax output); output in (1, e]
#pragma unroll
    for (int k = 0; k < 4; k++) {
        int j = t + k * 256;
        g_E[base + j] = __expf(e[k] * inv);
    }
}

// ---------------------------------------------------------------------------
// colsum of E after init (full-height 64-column stripes)
// ---------------------------------------------------------------------------
__global__ __launch_bounds__(256) void k_colsum0() {
    const int b = blockIdx.y, j0 = blockIdx.x * 64;
    const int t = threadIdx.x, tc = t & 63, tr = t >> 6;
    const size_t cb = (size_t)b * NN * NN + j0 + tc;
    float acc = 0.f;
#pragma unroll 8
    for (int r = tr; r < NN; r += 4) acc += g_E[cb + (size_t)r * NN];
    __shared__ float part[4][64];
    part[tr][tc] = acc;
    __syncthreads();
    if (t < 64) g_colsum[b * NN + j0 + t] = (part[0][t] + part[1][t]) + (part[2][t] + part[3][t]);
}

// ---------------------------------------------------------------------------
// Column-softmax half-step: z = E * inv_colsum[j]; E <- exp(z) (in place);
// rowsum <- sum_j exp(z). Block covers 8 full rows. 4096 blocks.
// ---------------------------------------------------------------------------
__global__ __launch_bounds__(256) void k_colstep() {
    const int b = blockIdx.y, r0 = blockIdx.x * 8, t = threadIdx.x;
    __shared__ float inv_cs[NN];
    __shared__ float part[8][256];
    for (int j = t; j < NN; j += 256) inv_cs[j] = 1.0f / g_colsum[b * NN + j];
    __syncthreads();
#pragma unroll
    for (int rr = 0; rr < 8; rr++) {
        const size_t base = ((size_t)b * NN + r0 + rr) * NN;
        float p = 0.f;
#pragma unroll
        for (int k = 0; k < 4; k++) {
            int j = t + k * 256;
            float e = __expf(g_E[base + j] * inv_cs[j]);
            g_E[base + j] = e;
            p += e;
        }
        part[rr][t] = p;
    }
    __syncthreads();
    const int w = t >> 5, lane = t & 31;
    float s = 0.f;
#pragma unroll
    for (int k = 0; k < 8; k++) s += part[w][lane + k * 32];
#pragma unroll
    for (int o = 16; o > 0; o >>= 1) s += __shfl_xor_sync(0xffffffffu, s, o);
    if (lane == 0) g_rowsum[b * NN + r0 + w] = s;
}

// ---------------------------------------------------------------------------
// Row-softmax half-step: y = E * inv_rowsum[i]; E <- exp(y) (in place);
// colsum <- sum_i exp(y). Full-height 64-col stripes. 512 blocks.
// ---------------------------------------------------------------------------
__global__ __launch_bounds__(256) void k_rowstep() {
    const int b = blockIdx.y, j0 = blockIdx.x * 64;
    const int t = threadIdx.x, tc = t & 63, tr = t >> 6;
    __shared__ float inv_rs[NN];
    for (int i = t; i < NN; i += 256) inv_rs[i] = 1.0f / g_rowsum[b * NN + i];
    __syncthreads();
    const size_t cb = (size_t)b * NN * NN + j0 + tc;
    float acc = 0.f;
#pragma unroll 8
    for (int r = tr; r < NN; r += 4) {
        size_t idx = cb + (size_t)r * NN;
        float e = __expf(g_E[idx] * inv_rs[r]);
        g_E[idx] = e;
        acc += e;
    }
    __shared__ float part[4][64];
    part[tr][tc] = acc;
    __syncthreads();
    if (t < 64) g_colsum[b * NN + j0 + t] = (part[0][t] + part[1][t]) + (part[2][t] + part[3][t]);
}

// ---------------------------------------------------------------------------
// Final: out = (E * inv_colsum[j]) @ feature = E @ (inv_colsum ⊙ feature)
// Classic 128x128 tile SGEMM, BK=16, 256 threads, 8x8 microtile.
// ---------------------------------------------------------------------------
__global__ __launch_bounds__(256) void k_gemm(const float* __restrict__ feat,
                                              float* __restrict__ out) {
    const int b = blockIdx.y, i0 = blockIdx.x * 128, t = threadIdx.x;
    const int tx = t & 15, ty = t >> 4;
    __shared__ float inv_cs[NN];
    __shared__ float sA[128][16];  // E tile [i][k]
    __shared__ float sB[16][128];  // scaled feature tile [k][c]
    for (int j = t; j < NN; j += 256) inv_cs[j] = 1.0f / g_colsum[b * NN + j];
    __syncthreads();

    float acc[8][8];
#pragma unroll
    for (int r = 0; r < 8; r++)
#pragma unroll
        for (int c = 0; c < 8; c++) acc[r][c] = 0.f;

    const float* Eb = g_E + (size_t)b * NN * NN;
    const float* Fb = feat + (size_t)b * NN * FF;
    const int arow = t >> 1, ak = (t & 1) * 8;
    const int bk = t >> 4, bc = (t & 15) * 8;

    for (int k0 = 0; k0 < NN; k0 += 16) {
        float4 a0 = *(const float4*)&Eb[(size_t)(i0 + arow) * NN + k0 + ak];
        float4 a1 = *(const float4*)&Eb[(size_t)(i0 + arow) * NN + k0 + ak + 4];
        *(float4*)&sA[arow][ak] = a0;
        *(float4*)&sA[arow][ak + 4] = a1;

        const float sc = inv_cs[k0 + bk];
        float4 b0 = *(const float4*)&Fb[(size_t)(k0 + bk) * FF + bc];
        float4 b1 = *(const float4*)&Fb[(size_t)(k0 + bk) * FF + bc + 4];
        b0.x *= sc; b0.y *= sc; b0.z *= sc; b0.w *= sc;
        b1.x *= sc; b1.y *= sc; b1.z *= sc; b1.w *= sc;
        *(float4*)&sB[bk][bc] = b0;
        *(float4*)&sB[bk][bc + 4] = b1;
        __syncthreads();

#pragma unroll
        for (int kk = 0; kk < 16; kk++) {
            float a[8], bb[8];
#pragma unroll
            for (int r = 0; r < 8; r++) a[r] = sA[ty * 8 + r][kk];
            float4 v0 = *(const float4*)&sB[kk][tx * 8];
            float4 v1 = *(const float4*)&sB[kk][tx * 8 + 4];
            bb[0] = v0.x; bb[1] = v0.y; bb[2] = v0.z; bb[3] = v0.w;
            bb[4] = v1.x; bb[5] = v1.y; bb[6] = v1.z; bb[7] = v1.w;
#pragma unroll
            for (int r = 0; r < 8; r++)
#pragma unroll
                for (int c = 0; c < 8; c++) acc[r][c] = fmaf(a[r], bb[c], acc[r][c]);
        }
        __syncthreads();
    }

#pragma unroll
    for (int r = 0; r < 8; r++) {
        float4 o0 = make_float4(acc[r][0], acc[r][1], acc[r][2], acc[r][3]);
        float4 o1 = make_float4(acc[r][4], acc[r][5], acc[r][6], acc[r][7]);
        size_t ob = ((size_t)b * NN + i0 + ty * 8 + r) * FF + tx * 8;
        *(float4*)&out[ob] = o0;
        *(float4*)&out[ob + 4] = o1;
    }
}

// ---------------------------------------------------------------------------
// Schedule:
//   init            = row softmax #1         (E, then colsum via k_colsum0)
//   9 x (colstep, rowstep) = col #1..#9, row #2..#10
//   gemm            = col softmax #10 folded into the matmul
// ---------------------------------------------------------------------------
extern "C" void kernel_launch(void* const* d_in, const int* in_sizes, int n_in,
                              void* d_out, int out_size) {
    const float* feat = (const float*)d_in[0];   // [B,N,F]
    const float* tmpl = (const float*)d_in[1];   // [1,N,N]
    const float* uni  = (const float*)d_in[2];   // [B,N,N]
    float* out = (float*)d_out;                  // [B,N,F]

    k_init<<<dim3(NN, BB), 256>>>(tmpl, uni);
    k_colsum0<<<dim3(NN / 64, BB), 256>>>();
    for (int it = 0; it < 9; ++it) {
        k_colstep<<<dim3(NN / 8, BB), 256>>>();
        k_rowstep<<<dim3(NN / 64, BB), 256>>>();
    }
    k_gemm<<<dim3(NN / 128, BB), 256>>>(feat, out);
}

// round 5
// speedup vs baseline: 1.4036x; 1.4036x over previous
#include <cuda_runtime.h>
#include <math.h>

#define BB 32
#define NN 1024
#define FF 128
#define RPB 8               // rows per fused block
#define NBLK (NN / RPB)     // 128 partial slabs per (b)

// Scratch: E = exp(current matrix), updated in place each fused half-step pair.
__device__ float g_E[BB * NN * NN];
__device__ float g_colsum[BB * NN];
__device__ float g_part[NBLK * BB * NN];   // per-block colsum partials (16MB)

// ---------------------------------------------------------------------------
// Init: m = (tmpl + gumbel)/T ; row softmax #1 (with max) ; store E = exp(y1)
// and emit colsum partials. Block = 8 full rows, 256 threads, float4 lanes.
// ---------------------------------------------------------------------------
__global__ __launch_bounds__(256, 4) void k_init(const float* __restrict__ tmpl,
                                                 const float* __restrict__ uni) {
    const int b = blockIdx.y, r0 = blockIdx.x * RPB, t = threadIdx.x;
    const int j0 = t * 4;
    __shared__ float part[RPB][256];
    __shared__ float rred[RPB];

    float4 x4[RPB];
#pragma unroll
    for (int rr = 0; rr < RPB; rr++) {
        const int row = r0 + rr;
        float4 u = *(const float4*)&uni[((size_t)b * NN + row) * NN + j0];
        float4 tm = *(const float4*)&tmpl[(size_t)row * NN + j0];
        // accurate logf: needed for correct Gumbel tail when u ~ 1
        float4 x;
        x.x = (tm.x - logf(-logf(u.x + 1e-12f) + 1e-12f)) * 5.0f;
        x.y = (tm.y - logf(-logf(u.y + 1e-12f) + 1e-12f)) * 5.0f;
        x.z = (tm.z - logf(-logf(u.z + 1e-12f) + 1e-12f)) * 5.0f;
        x.w = (tm.w - logf(-logf(u.w + 1e-12f) + 1e-12f)) * 5.0f;
        x4[rr] = x;
        part[rr][t] = fmaxf(fmaxf(x.x, x.y), fmaxf(x.z, x.w));
    }
    __syncthreads();
    // per-row max: warp w reduces row w
    {
        const int w = t >> 5, lane = t & 31;
        float v = part[w][lane];
#pragma unroll
        for (int k = 1; k < 8; k++) v = fmaxf(v, part[w][lane + k * 32]);
#pragma unroll
        for (int o = 16; o > 0; o >>= 1) v = fmaxf(v, __shfl_xor_sync(0xffffffffu, v, o));
        if (lane == 0) rred[w] = v;
    }
    __syncthreads();
#pragma unroll
    for (int rr = 0; rr < RPB; rr++) {
        const float mx = rred[rr];
        float4 e;
        e.x = __expf(x4[rr].x - mx);
        e.y = __expf(x4[rr].y - mx);
        e.z = __expf(x4[rr].z - mx);
        e.w = __expf(x4[rr].w - mx);
        x4[rr] = e;
        part[rr][t] = (e.x + e.y) + (e.z + e.w);
    }
    __syncthreads();
    {
        const int w = t >> 5, lane = t & 31;
        float v = part[w][lane];
#pragma unroll
        for (int k = 1; k < 8; k++) v += part[w][lane + k * 32];
#pragma unroll
        for (int o = 16; o > 0; o >>= 1) v += __shfl_xor_sync(0xffffffffu, v, o);
        if (lane == 0) rred[w] = 1.0f / v;
    }
    __syncthreads();
    float4 cs = make_float4(0.f, 0.f, 0.f, 0.f);
#pragma unroll
    for (int rr = 0; rr < RPB; rr++) {
        const float inv = rred[rr];
        float4 E;
        E.x = __expf(x4[rr].x * inv);
        E.y = __expf(x4[rr].y * inv);
        E.z = __expf(x4[rr].z * inv);
        E.w = __expf(x4[rr].w * inv);
        *(float4*)&g_E[((size_t)b * NN + r0 + rr) * NN + j0] = E;
        cs.x += E.x; cs.y += E.y; cs.z += E.z; cs.w += E.w;
    }
    *(float4*)&g_part[((size_t)blockIdx.x * BB + b) * NN + j0] = cs;
}

// ---------------------------------------------------------------------------
// Reduce colsum partials (deterministic fixed order). 512 blocks.
// ---------------------------------------------------------------------------
__global__ __launch_bounds__(256) void k_reduce() {
    const int b = blockIdx.y, c0 = blockIdx.x * 64, t = threadIdx.x;
    const int tc = t & 63, tp = t >> 6;
    float s = 0.f;
#pragma unroll 8
    for (int p = tp; p < NBLK; p += 4)
        s += g_part[((size_t)p * BB + b) * NN + c0 + tc];
    __shared__ float sm[4][64];
    sm[tp][tc] = s;
    __syncthreads();
    if (t < 64)
        g_colsum[b * NN + c0 + t] = (sm[0][t] + sm[1][t]) + (sm[2][t] + sm[3][t]);
}

// ---------------------------------------------------------------------------
// Fused pair: col softmax half-step + row softmax half-step, one R+W pass.
//   e  = exp(E * inv_colsum[j])        (col softmax output, exponentiated)
//   E' = exp(e * inv_rowsum_in_block)  (row softmax output, exponentiated)
// Block = 8 full rows: rowsum is exact in-block; colsum emitted as partials.
// ---------------------------------------------------------------------------
__global__ __launch_bounds__(256, 4) void k_fused() {
    const int b = blockIdx.y, r0 = blockIdx.x * RPB, t = threadIdx.x;
    const int j0 = t * 4;
    __shared__ float part[RPB][256];
    __shared__ float rinv[RPB];

    float4 c = *(const float4*)&g_colsum[b * NN + j0];
    const float4 ic = make_float4(1.0f / c.x, 1.0f / c.y, 1.0f / c.z, 1.0f / c.w);

    float4 e4[RPB];
#pragma unroll
    for (int rr = 0; rr < RPB; rr++) {
        float4 E = *(const float4*)&g_E[((size_t)b * NN + r0 + rr) * NN + j0];
        float4 e;
        e.x = __expf(E.x * ic.x);
        e.y = __expf(E.y * ic.y);
        e.z = __expf(E.z * ic.z);
        e.w = __expf(E.w * ic.w);
        e4[rr] = e;
        part[rr][t] = (e.x + e.y) + (e.z + e.w);
    }
    __syncthreads();
    {
        const int w = t >> 5, lane = t & 31;
        float v = part[w][lane];
#pragma unroll
        for (int k = 1; k < 8; k++) v += part[w][lane + k * 32];
#pragma unroll
        for (int o = 16; o > 0; o >>= 1) v += __shfl_xor_sync(0xffffffffu, v, o);
        if (lane == 0) rinv[w] = 1.0f / v;
    }
    __syncthreads();
    float4 cs = make_float4(0.f, 0.f, 0.f, 0.f);
#pragma unroll
    for (int rr = 0; rr < RPB; rr++) {
        const float ir = rinv[rr];
        float4 E;
        E.x = __expf(e4[rr].x * ir);
        E.y = __expf(e4[rr].y * ir);
        E.z = __expf(e4[rr].z * ir);
        E.w = __expf(e4[rr].w * ir);
        *(float4*)&g_E[((size_t)b * NN + r0 + rr) * NN + j0] = E;
        cs.x += E.x; cs.y += E.y; cs.z += E.z; cs.w += E.w;
    }
    *(float4*)&g_part[((size_t)blockIdx.x * BB + b) * NN + j0] = cs;
}

// ---------------------------------------------------------------------------
// Final: out = (E * inv_colsum[j]) @ feature = E @ (inv_colsum ⊙ feature)
// 128x128 tile SGEMM, BK=16, 256 threads, 8x8 microtile.
// ---------------------------------------------------------------------------
__global__ __launch_bounds__(256) void k_gemm(const float* __restrict__ feat,
                                              float* __restrict__ out) {
    const int b = blockIdx.y, i0 = blockIdx.x * 128, t = threadIdx.x;
    const int tx = t & 15, ty = t >> 4;
    __shared__ float inv_cs[NN];
    __shared__ float sA[128][16];
    __shared__ float sB[16][128];
    for (int j = t; j < NN; j += 256) inv_cs[j] = 1.0f / g_colsum[b * NN + j];
    __syncthreads();

    float acc[8][8];
#pragma unroll
    for (int r = 0; r < 8; r++)
#pragma unroll
        for (int c = 0; c < 8; c++) acc[r][c] = 0.f;

    const float* Eb = g_E + (size_t)b * NN * NN;
    const float* Fb = feat + (size_t)b * NN * FF;
    const int arow = t >> 1, ak = (t & 1) * 8;
    const int bk = t >> 4, bc = (t & 15) * 8;

    for (int k0 = 0; k0 < NN; k0 += 16) {
        float4 a0 = *(const float4*)&Eb[(size_t)(i0 + arow) * NN + k0 + ak];
        float4 a1 = *(const float4*)&Eb[(size_t)(i0 + arow) * NN + k0 + ak + 4];
        *(float4*)&sA[arow][ak] = a0;
        *(float4*)&sA[arow][ak + 4] = a1;

        const float sc = inv_cs[k0 + bk];
        float4 b0 = *(const float4*)&Fb[(size_t)(k0 + bk) * FF + bc];
        float4 b1 = *(const float4*)&Fb[(size_t)(k0 + bk) * FF + bc + 4];
        b0.x *= sc; b0.y *= sc; b0.z *= sc; b0.w *= sc;
        b1.x *= sc; b1.y *= sc; b1.z *= sc; b1.w *= sc;
        *(float4*)&sB[bk][bc] = b0;
        *(float4*)&sB[bk][bc + 4] = b1;
        __syncthreads();

#pragma unroll
        for (int kk = 0; kk < 16; kk++) {
            float a[8], bb[8];
#pragma unroll
            for (int r = 0; r < 8; r++) a[r] = sA[ty * 8 + r][kk];
            float4 v0 = *(const float4*)&sB[kk][tx * 8];
            float4 v1 = *(const float4*)&sB[kk][tx * 8 + 4];
            bb[0] = v0.x; bb[1] = v0.y; bb[2] = v0.z; bb[3] = v0.w;
            bb[4] = v1.x; bb[5] = v1.y; bb[6] = v1.z; bb[7] = v1.w;
#pragma unroll
            for (int r = 0; r < 8; r++)
#pragma unroll
                for (int c = 0; c < 8; c++) acc[r][c] = fmaf(a[r], bb[c], acc[r][c]);
        }
        __syncthreads();
    }

#pragma unroll
    for (int r = 0; r < 8; r++) {
        float4 o0 = make_float4(acc[r][0], acc[r][1], acc[r][2], acc[r][3]);
        float4 o1 = make_float4(acc[r][4], acc[r][5], acc[r][6], acc[r][7]);
        size_t ob = ((size_t)b * NN + i0 + ty * 8 + r) * FF + tx * 8;
        *(float4*)&out[ob] = o0;
        *(float4*)&out[ob + 4] = o1;
    }
}

// ---------------------------------------------------------------------------
// Schedule: init = row#1 (+colsum partials); 9 x fused = (col#k,row#k+1);
// gemm folds col#10 into the matmul.
// ---------------------------------------------------------------------------
extern "C" void kernel_launch(void* const* d_in, const int* in_sizes, int n_in,
                              void* d_out, int out_size) {
    const float* feat = (const float*)d_in[0];   // [B,N,F]
    const float* tmpl = (const float*)d_in[1];   // [1,N,N]
    const float* uni  = (const float*)d_in[2];   // [B,N,N]
    float* out = (float*)d_out;                  // [B,N,F]

    k_init<<<dim3(NBLK, BB), 256>>>(tmpl, uni);
    k_reduce<<<dim3(NN / 64, BB), 256>>>();
    for (int it = 0; it < 9; ++it) {
        k_fused<<<dim3(NBLK, BB), 256>>>();
        k_reduce<<<dim3(NN / 64, BB), 256>>>();
    }
    k_gemm<<<dim3(NN / 128, BB), 256>>>(feat, out);
}

// round 9
// speedup vs baseline: 1.6892x; 1.2035x over previous
#include <cuda_runtime.h>
#include <cuda_bf16.h>
#include <math.h>
#include <stdint.h>

#define BB 32
#define NN 1024
#define FF 128
#define RPB 8
#define NBLK (NN / RPB)
#define GC 32            // GEMM K-chunks
#define CK 32            // k elements per chunk

__device__ float g_E[BB * NN * NN];               // 128MB fp32 (Sinkhorn state)
__device__ float g_colsum[BB * NN];
__device__ float g_part[NBLK * BB * NN];          // 16MB colsum partials
__device__ __nv_bfloat16 g_Eh[BB * NN * NN];      // 64MB final E hi
__device__ __nv_bfloat16 g_El[BB * NN * NN];      // 64MB final E lo
__device__ __nv_bfloat16 g_B[BB * NN * 256];      // 16MB scaled feature [hi128|lo128] per row

// ---------------- PTX helpers (plain compute_103-safe) ----------------
__device__ __forceinline__ uint32_t smem_u32(const void* p) {
    uint32_t a;
    asm("{ .reg .u64 t; cvta.to.shared.u64 t, %1; cvt.u32.u64 %0, t; }" : "=r"(a) : "l"(p));
    return a;
}
#define CP16(dst, src) asm volatile("cp.async.cg.shared.global [%0], [%1], 16;" :: "r"(dst), "l"(src))
#define CP_COMMIT()    asm volatile("cp.async.commit_group;" ::: "memory")
#define CP_WAIT1()     asm volatile("cp.async.wait_group 1;" ::: "memory")
#define CP_WAIT0()     asm volatile("cp.async.wait_group 0;" ::: "memory")

__device__ __forceinline__ void ldsm_x4(uint32_t* r, uint32_t addr) {
    asm volatile("ldmatrix.sync.aligned.m8n8.x4.shared.b16 {%0,%1,%2,%3}, [%4];"
                 : "=r"(r[0]), "=r"(r[1]), "=r"(r[2]), "=r"(r[3]) : "r"(addr));
}
__device__ __forceinline__ void ldsm_x4_t(uint32_t* r, uint32_t addr) {
    asm volatile("ldmatrix.sync.aligned.m8n8.x4.trans.shared.b16 {%0,%1,%2,%3}, [%4];"
                 : "=r"(r[0]), "=r"(r[1]), "=r"(r[2]), "=r"(r[3]) : "r"(addr));
}
__device__ __forceinline__ void mma_bf16(float* d, const uint32_t* a, const uint32_t* b) {
    asm volatile("mma.sync.aligned.m16n8k16.row.col.f32.bf16.bf16.f32 "
                 "{%0,%1,%2,%3}, {%4,%5,%6,%7}, {%8,%9}, {%0,%1,%2,%3};"
                 : "+f"(d[0]), "+f"(d[1]), "+f"(d[2]), "+f"(d[3])
                 : "r"(a[0]), "r"(a[1]), "r"(a[2]), "r"(a[3]), "r"(b[0]), "r"(b[1]));
}

union PackB4 { __nv_bfloat16 h[4]; uint2 u; };

// ===========================================================================
// Sinkhorn kernels (R5 passing versions)
// ===========================================================================
__global__ __launch_bounds__(256, 4) void k_init(const float* __restrict__ tmpl,
                                                 const float* __restrict__ uni) {
    const int b = blockIdx.y, r0 = blockIdx.x * RPB, t = threadIdx.x;
    const int j0 = t * 4;
    __shared__ float part[RPB][256];
    __shared__ float rred[RPB];

    float4 x4[RPB];
#pragma unroll
    for (int rr = 0; rr < RPB; rr++) {
        const int row = r0 + rr;
        float4 u = *(const float4*)&uni[((size_t)b * NN + row) * NN + j0];
        float4 tm = *(const float4*)&tmpl[(size_t)row * NN + j0];
        float4 x;
        x.x = (tm.x - logf(-logf(u.x + 1e-12f) + 1e-12f)) * 5.0f;
        x.y = (tm.y - logf(-logf(u.y + 1e-12f) + 1e-12f)) * 5.0f;
        x.z = (tm.z - logf(-logf(u.z + 1e-12f) + 1e-12f)) * 5.0f;
        x.w = (tm.w - logf(-logf(u.w + 1e-12f) + 1e-12f)) * 5.0f;
        x4[rr] = x;
        part[rr][t] = fmaxf(fmaxf(x.x, x.y), fmaxf(x.z, x.w));
    }
    __syncthreads();
    {
        const int w = t >> 5, lane = t & 31;
        float v = part[w][lane];
#pragma unroll
        for (int k = 1; k < 8; k++) v = fmaxf(v, part[w][lane + k * 32]);
#pragma unroll
        for (int o = 16; o > 0; o >>= 1) v = fmaxf(v, __shfl_xor_sync(0xffffffffu, v, o));
        if (lane == 0) rred[w] = v;
    }
    __syncthreads();
#pragma unroll
    for (int rr = 0; rr < RPB; rr++) {
        const float mx = rred[rr];
        float4 e;
        e.x = __expf(x4[rr].x - mx);
        e.y = __expf(x4[rr].y - mx);
        e.z = __expf(x4[rr].z - mx);
        e.w = __expf(x4[rr].w - mx);
        x4[rr] = e;
        part[rr][t] = (e.x + e.y) + (e.z + e.w);
    }
    __syncthreads();
    {
        const int w = t >> 5, lane = t & 31;
        float v = part[w][lane];
#pragma unroll
        for (int k = 1; k < 8; k++) v += part[w][lane + k * 32];
#pragma unroll
        for (int o = 16; o > 0; o >>= 1) v += __shfl_xor_sync(0xffffffffu, v, o);
        if (lane == 0) rred[w] = 1.0f / v;
    }
    __syncthreads();
    float4 cs = make_float4(0.f, 0.f, 0.f, 0.f);
#pragma unroll
    for (int rr = 0; rr < RPB; rr++) {
        const float inv = rred[rr];
        float4 E;
        E.x = __expf(x4[rr].x * inv);
        E.y = __expf(x4[rr].y * inv);
        E.z = __expf(x4[rr].z * inv);
        E.w = __expf(x4[rr].w * inv);
        *(float4*)&g_E[((size_t)b * NN + r0 + rr) * NN + j0] = E;
        cs.x += E.x; cs.y += E.y; cs.z += E.z; cs.w += E.w;
    }
    *(float4*)&g_part[((size_t)blockIdx.x * BB + b) * NN + j0] = cs;
}

__global__ __launch_bounds__(256) void k_reduce() {
    const int b = blockIdx.y, g = blockIdx.x, t = threadIdx.x;
    const int c4 = t & 31, p0 = t >> 5;
    const float4* P = (const float4*)g_part;
    float4 s = make_float4(0.f, 0.f, 0.f, 0.f);
#pragma unroll
    for (int p = p0; p < NBLK; p += 8) {
        float4 v = P[((size_t)p * BB + b) * (NN / 4) + g * 32 + c4];
        s.x += v.x; s.y += v.y; s.z += v.z; s.w += v.w;
    }
    __shared__ float4 sm[8][32];
    sm[p0][c4] = s;
    __syncthreads();
    if (t < 32) {
        float4 a = sm[0][t];
#pragma unroll
        for (int p = 1; p < 8; p++) {
            float4 v = sm[p][t];
            a.x += v.x; a.y += v.y; a.z += v.z; a.w += v.w;
        }
        *(float4*)&g_colsum[b * NN + g * 128 + t * 4] = a;
    }
}

__global__ __launch_bounds__(256, 4) void k_fused() {
    const int b = blockIdx.y, r0 = blockIdx.x * RPB, t = threadIdx.x;
    const int j0 = t * 4;
    __shared__ float part[RPB][256];
    __shared__ float rinv[RPB];

    float4 c = *(const float4*)&g_colsum[b * NN + j0];
    const float4 ic = make_float4(1.0f / c.x, 1.0f / c.y, 1.0f / c.z, 1.0f / c.w);

    float4 e4[RPB];
#pragma unroll
    for (int rr = 0; rr < RPB; rr++) {
        float4 E = *(const float4*)&g_E[((size_t)b * NN + r0 + rr) * NN + j0];
        float4 e;
        e.x = __expf(E.x * ic.x);
        e.y = __expf(E.y * ic.y);
        e.z = __expf(E.z * ic.z);
        e.w = __expf(E.w * ic.w);
        e4[rr] = e;
        part[rr][t] = (e.x + e.y) + (e.z + e.w);
    }
    __syncthreads();
    {
        const int w = t >> 5, lane = t & 31;
        float v = part[w][lane];
#pragma unroll
        for (int k = 1; k < 8; k++) v += part[w][lane + k * 32];
#pragma unroll
        for (int o = 16; o > 0; o >>= 1) v += __shfl_xor_sync(0xffffffffu, v, o);
        if (lane == 0) rinv[w] = 1.0f / v;
    }
    __syncthreads();
    float4 cs = make_float4(0.f, 0.f, 0.f, 0.f);
#pragma unroll
    for (int rr = 0; rr < RPB; rr++) {
        const float ir = rinv[rr];
        float4 E;
        E.x = __expf(e4[rr].x * ir);
        E.y = __expf(e4[rr].y * ir);
        E.z = __expf(e4[rr].z * ir);
        E.w = __expf(e4[rr].w * ir);
        *(float4*)&g_E[((size_t)b * NN + r0 + rr) * NN + j0] = E;
        cs.x += E.x; cs.y += E.y; cs.z += E.z; cs.w += E.w;
    }
    *(float4*)&g_part[((size_t)blockIdx.x * BB + b) * NN + j0] = cs;
}

// Last fused iteration: same math, but store E as bf16 hi/lo (for HMMA GEMM).
__global__ __launch_bounds__(256, 4) void k_fused_last() {
    const int b = blockIdx.y, r0 = blockIdx.x * RPB, t = threadIdx.x;
    const int j0 = t * 4;
    __shared__ float part[RPB][256];
    __shared__ float rinv[RPB];

    float4 c = *(const float4*)&g_colsum[b * NN + j0];
    const float4 ic = make_float4(1.0f / c.x, 1.0f / c.y, 1.0f / c.z, 1.0f / c.w);

    float4 e4[RPB];
#pragma unroll
    for (int rr = 0; rr < RPB; rr++) {
        float4 E = *(const float4*)&g_E[((size_t)b * NN + r0 + rr) * NN + j0];
        float4 e;
        e.x = __expf(E.x * ic.x);
        e.y = __expf(E.y * ic.y);
        e.z = __expf(E.z * ic.z);
        e.w = __expf(E.w * ic.w);
        e4[rr] = e;
        part[rr][t] = (e.x + e.y) + (e.z + e.w);
    }
    __syncthreads();
    {
        const int w = t >> 5, lane = t & 31;
        float v = part[w][lane];
#pragma unroll
        for (int k = 1; k < 8; k++) v += part[w][lane + k * 32];
#pragma unroll
        for (int o = 16; o > 0; o >>= 1) v += __shfl_xor_sync(0xffffffffu, v, o);
        if (lane == 0) rinv[w] = 1.0f / v;
    }
    __syncthreads();
    float4 cs = make_float4(0.f, 0.f, 0.f, 0.f);
#pragma unroll
    for (int rr = 0; rr < RPB; rr++) {
        const float ir = rinv[rr];
        float Ex = __expf(e4[rr].x * ir);
        float Ey = __expf(e4[rr].y * ir);
        float Ez = __expf(e4[rr].z * ir);
        float Ew = __expf(e4[rr].w * ir);
        PackB4 H, L;
        H.h[0] = __float2bfloat16(Ex); L.h[0] = __float2bfloat16(Ex - __bfloat162float(H.h[0]));
        H.h[1] = __float2bfloat16(Ey); L.h[1] = __float2bfloat16(Ey - __bfloat162float(H.h[1]));
        H.h[2] = __float2bfloat16(Ez); L.h[2] = __float2bfloat16(Ez - __bfloat162float(H.h[2]));
        H.h[3] = __float2bfloat16(Ew); L.h[3] = __float2bfloat16(Ew - __bfloat162float(H.h[3]));
        const size_t idx = ((size_t)b * NN + r0 + rr) * NN + j0;
        *(uint2*)&g_Eh[idx] = H.u;
        *(uint2*)&g_El[idx] = L.u;
        cs.x += Ex; cs.y += Ey; cs.z += Ez; cs.w += Ew;
    }
    *(float4*)&g_part[((size_t)blockIdx.x * BB + b) * NN + j0] = cs;
}

// ===========================================================================
// B precompute: g_B[b][k][0:128]=hi, [128:256]=lo of inv_colsum[k]*feat[k][f]
// ===========================================================================
__global__ __launch_bounds__(256) void k_prepB(const float* __restrict__ feat) {
    const int b = blockIdx.y, k = blockIdx.x * 8 + (threadIdx.x >> 5);
    const int f4 = (threadIdx.x & 31) * 4;
    const float ic = 1.0f / g_colsum[b * NN + k];
    float4 v = *(const float4*)&feat[((size_t)b * NN + k) * FF + f4];
    v.x *= ic; v.y *= ic; v.z *= ic; v.w *= ic;
    PackB4 H, L;
    H.h[0] = __float2bfloat16(v.x); L.h[0] = __float2bfloat16(v.x - __bfloat162float(H.h[0]));
    H.h[1] = __float2bfloat16(v.y); L.h[1] = __float2bfloat16(v.y - __bfloat162float(H.h[1]));
    H.h[2] = __float2bfloat16(v.z); L.h[2] = __float2bfloat16(v.z - __bfloat162float(H.h[2]));
    H.h[3] = __float2bfloat16(v.w); L.h[3] = __float2bfloat16(v.w - __bfloat162float(H.h[3]));
    const size_t rb = ((size_t)b * NN + k) * 256;
    *(uint2*)&g_B[rb + f4] = H.u;
    *(uint2*)&g_B[rb + 128 + f4] = L.u;
}

// ===========================================================================
// HMMA bf16 split GEMM: out[i][f] = sum_k (Eh+El)[i][k] * (Bh+Bl)[k][f]
// (dropping the lo*lo term). 128x128 tile per block, K-chunks of 32,
// cp.async double buffer, ldmatrix fragments, mma.sync m16n8k16 bf16.
// Smem buffer (37888B each, x2):
//   A: hi [128][stride 80B] @0, lo @10240      (row = 32 bf16 = 64B, pad to 80)
//   B: hi [32][stride 272B] @20480, lo @+8704  (row = 128 bf16 = 256B, pad 272)
// ===========================================================================
#define ABUF 37888
#define AHI 0
#define ALO 10240
#define BHI 20480
#define BLO_OFF 8704

__global__ __launch_bounds__(256) void k_gemm(float* __restrict__ out) {
    extern __shared__ char smem[];
    const int b = blockIdx.y, i0 = blockIdx.x * 128, t = threadIdx.x;
    const int wid = t >> 5, lane = t & 31;
    const int wm = wid & 3, wn = wid >> 2;
    const uint32_t sb = smem_u32(smem);

    // per-thread load slots
    const int rowA = t >> 1, halfA = (t & 1) * 32;               // A: 2x16B hi + 2x16B lo
    const int rowB = t >> 3, pB = (t & 7) * 64;                  // B: 4x16B run (byte off)
    const char* srcAh = (const char*)(g_Eh + ((size_t)b * NN + i0 + rowA) * NN) + halfA;
    const char* srcAl = (const char*)(g_El + ((size_t)b * NN + i0 + rowA) * NN) + halfA;
    const char* srcB  = (const char*)(g_B + (size_t)b * NN * 256) + rowB * 512 + pB;
    const uint32_t dAh = sb + AHI + rowA * 80 + halfA;
    const uint32_t dAl = sb + ALO + rowA * 80 + halfA;
    const uint32_t dB  = sb + BHI + (pB < 256 ? 0 : BLO_OFF) + rowB * 272 + (pB & 255);

#define ISSUE_CHUNK(cc)  do {                                            \
        const int _s = (cc) & 1;                                         \
        const size_t _ao = (size_t)(cc) * CK * 2;                        \
        CP16(dAh + _s * ABUF,      srcAh + _ao);                         \
        CP16(dAh + _s * ABUF + 16, srcAh + _ao + 16);                    \
        CP16(dAl + _s * ABUF,      srcAl + _ao);                         \
        CP16(dAl + _s * ABUF + 16, srcAl + _ao + 16);                    \
        const size_t _bo = (size_t)(cc) * CK * 512;                      \
        CP16(dB + _s * ABUF,      srcB + _bo);                           \
        CP16(dB + _s * ABUF + 16, srcB + _bo + 16);                      \
        CP16(dB + _s * ABUF + 32, srcB + _bo + 32);                      \
        CP16(dB + _s * ABUF + 48, srcB + _bo + 48);                      \
        CP_COMMIT();                                                     \
    } while (0)

    float acc[2][8][4];
#pragma unroll
    for (int mf = 0; mf < 2; mf++)
#pragma unroll
        for (int nf = 0; nf < 8; nf++)
#pragma unroll
            for (int q = 0; q < 4; q++) acc[mf][nf][q] = 0.f;

    ISSUE_CHUNK(0);

    for (int c = 0; c < GC; ++c) {
        if (c < GC - 1) { ISSUE_CHUNK(c + 1); CP_WAIT1(); }
        else            { CP_WAIT0(); }
        __syncthreads();

        const uint32_t bufA = sb + (c & 1) * ABUF;
#pragma unroll
        for (int ks = 0; ks < 2; ks++) {
            uint32_t aH[2][4], aL[2][4];
#pragma unroll
            for (int mf = 0; mf < 2; mf++) {
                const int r0 = wm * 32 + mf * 16;
                const uint32_t ad = bufA + AHI + (r0 + (lane & 15)) * 80 + ks * 32 + (lane >> 4) * 16;
                ldsm_x4(aH[mf], ad);
                ldsm_x4(aL[mf], ad + (ALO - AHI));
            }
            uint32_t bH[4][4], bL[4][4];
#pragma unroll
            for (int ng = 0; ng < 4; ng++) {
                const int n0 = wn * 64 + ng * 16;
                const uint32_t bd = bufA + BHI + (ks * 16 + (lane & 15)) * 272 + n0 * 2 + (lane >> 4) * 16;
                ldsm_x4_t(bH[ng], bd);
                ldsm_x4_t(bL[ng], bd + BLO_OFF);
            }
#pragma unroll
            for (int mf = 0; mf < 2; mf++)
#pragma unroll
                for (int ng = 0; ng < 4; ng++)
#pragma unroll
                    for (int h = 0; h < 2; h++) {
                        float* d = acc[mf][ng * 2 + h];
                        mma_bf16(d, aH[mf], &bH[ng][h * 2]);
                        mma_bf16(d, aH[mf], &bL[ng][h * 2]);
                        mma_bf16(d, aL[mf], &bH[ng][h * 2]);
                    }
        }
        __syncthreads();
    }

    // epilogue
    const int gid = lane >> 2, t4 = lane & 3;
#pragma unroll
    for (int mf = 0; mf < 2; mf++) {
        const int row = i0 + wm * 32 + mf * 16 + gid;
#pragma unroll
        for (int nf = 0; nf < 8; nf++) {
            const int col = wn * 64 + nf * 8 + t4 * 2;
            const float* d = acc[mf][nf];
            *(float2*)&out[((size_t)b * NN + row) * FF + col]     = make_float2(d[0], d[1]);
            *(float2*)&out[((size_t)b * NN + row + 8) * FF + col] = make_float2(d[2], d[3]);
        }
    }
}

// ===========================================================================
extern "C" void kernel_launch(void* const* d_in, const int* in_sizes, int n_in,
                              void* d_out, int out_size) {
    const float* feat = (const float*)d_in[0];   // [B,N,F]
    const float* tmpl = (const float*)d_in[1];   // [1,N,N]
    const float* uni  = (const float*)d_in[2];   // [B,N,N]
    float* out = (float*)d_out;                  // [B,N,F]

    cudaFuncSetAttribute(k_gemm, cudaFuncAttributeMaxDynamicSharedMemorySize, 2 * ABUF);

    k_init<<<dim3(NBLK, BB), 256>>>(tmpl, uni);
    k_reduce<<<dim3(8, BB), 256>>>();
    for (int it = 0; it < 8; ++it) {
        k_fused<<<dim3(NBLK, BB), 256>>>();
        k_reduce<<<dim3(8, BB), 256>>>();
    }
    k_fused_last<<<dim3(NBLK, BB), 256>>>();
    k_reduce<<<dim3(8, BB), 256>>>();
    k_prepB<<<dim3(NN / 8, BB), 256>>>(feat);
    k_gemm<<<dim3(8, BB), 256, 2 * ABUF>>>(out);
}

// round 10
// speedup vs baseline: 1.9558x; 1.1578x over previous
#include <cuda_runtime.h>
#include <cuda_bf16.h>
#include <math.h>
#include <stdint.h>

#define BB 32
#define NN 1024
#define FF 128
#define RPB 8
#define NBLK (NN / RPB)
#define GC 32
#define CK 32

// State y (softmax output in [0,1]) as uint16 fixed-point: 64MB
__device__ unsigned short g_Y[BB * NN * NN];
__device__ float g_colsum[BB * NN];
__device__ float g_part[NBLK * BB * NN];          // 16MB colsum partials
__device__ __nv_bfloat16 g_Eh[BB * NN * NN];      // 64MB final E hi
__device__ __nv_bfloat16 g_El[BB * NN * NN];      // 64MB final E lo
__device__ __nv_bfloat16 g_B[BB * NN * 256];      // 16MB scaled feature [hi|lo]

// ---------------- fixed-point helpers ----------------
__device__ __forceinline__ ushort4 enc4(float x, float y, float z, float w) {
    ushort4 r;
    r.x = (unsigned short)__float2uint_rn(x * 65535.0f);
    r.y = (unsigned short)__float2uint_rn(y * 65535.0f);
    r.z = (unsigned short)__float2uint_rn(z * 65535.0f);
    r.w = (unsigned short)__float2uint_rn(w * 65535.0f);
    return r;
}
__device__ __forceinline__ float4 dec4(ushort4 u) {
    const float s = 1.0f / 65535.0f;
    return make_float4(u.x * s, u.y * s, u.z * s, u.w * s);
}

// ---------------- PTX helpers (plain compute_103-safe) ----------------
__device__ __forceinline__ uint32_t smem_u32(const void* p) {
    uint32_t a;
    asm("{ .reg .u64 t; cvta.to.shared.u64 t, %1; cvt.u32.u64 %0, t; }" : "=r"(a) : "l"(p));
    return a;
}
#define CP16(dst, src) asm volatile("cp.async.cg.shared.global [%0], [%1], 16;" :: "r"(dst), "l"(src))
#define CP_COMMIT()    asm volatile("cp.async.commit_group;" ::: "memory")
#define CP_WAIT1()     asm volatile("cp.async.wait_group 1;" ::: "memory")
#define CP_WAIT0()     asm volatile("cp.async.wait_group 0;" ::: "memory")

__device__ __forceinline__ void ldsm_x4(uint32_t* r, uint32_t addr) {
    asm volatile("ldmatrix.sync.aligned.m8n8.x4.shared.b16 {%0,%1,%2,%3}, [%4];"
                 : "=r"(r[0]), "=r"(r[1]), "=r"(r[2]), "=r"(r[3]) : "r"(addr));
}
__device__ __forceinline__ void ldsm_x4_t(uint32_t* r, uint32_t addr) {
    asm volatile("ldmatrix.sync.aligned.m8n8.x4.trans.shared.b16 {%0,%1,%2,%3}, [%4];"
                 : "=r"(r[0]), "=r"(r[1]), "=r"(r[2]), "=r"(r[3]) : "r"(addr));
}
__device__ __forceinline__ void mma_bf16(float* d, const uint32_t* a, const uint32_t* b) {
    asm volatile("mma.sync.aligned.m16n8k16.row.col.f32.bf16.bf16.f32 "
                 "{%0,%1,%2,%3}, {%4,%5,%6,%7}, {%8,%9}, {%0,%1,%2,%3};"
                 : "+f"(d[0]), "+f"(d[1]), "+f"(d[2]), "+f"(d[3])
                 : "r"(a[0]), "r"(a[1]), "r"(a[2]), "r"(a[3]), "r"(b[0]), "r"(b[1]));
}

union PackB4 { __nv_bfloat16 h[4]; uint2 u; };

// ===========================================================================
// Init: m = (tmpl+gumbel)/T ; row softmax #1 -> y1 (uint16) + colsum partials
// ===========================================================================
__global__ __launch_bounds__(256, 4) void k_init(const float* __restrict__ tmpl,
                                                 const float* __restrict__ uni) {
    const int b = blockIdx.y, r0 = blockIdx.x * RPB, t = threadIdx.x;
    const int j0 = t * 4;
    __shared__ float part[RPB][256];
    __shared__ float rred[RPB];

    float4 x4[RPB];
#pragma unroll
    for (int rr = 0; rr < RPB; rr++) {
        const int row = r0 + rr;
        float4 u = *(const float4*)&uni[((size_t)b * NN + row) * NN + j0];
        float4 tm = *(const float4*)&tmpl[(size_t)row * NN + j0];
        // inner log: accurate (u->1 cancellation); outer: MUFU __logf (well-conditioned)
        float4 x;
        x.x = (tm.x - __logf(-logf(u.x + 1e-12f) + 1e-12f)) * 5.0f;
        x.y = (tm.y - __logf(-logf(u.y + 1e-12f) + 1e-12f)) * 5.0f;
        x.z = (tm.z - __logf(-logf(u.z + 1e-12f) + 1e-12f)) * 5.0f;
        x.w = (tm.w - __logf(-logf(u.w + 1e-12f) + 1e-12f)) * 5.0f;
        x4[rr] = x;
        part[rr][t] = fmaxf(fmaxf(x.x, x.y), fmaxf(x.z, x.w));
    }
    __syncthreads();
    {
        const int w = t >> 5, lane = t & 31;
        float v = part[w][lane];
#pragma unroll
        for (int k = 1; k < 8; k++) v = fmaxf(v, part[w][lane + k * 32]);
#pragma unroll
        for (int o = 16; o > 0; o >>= 1) v = fmaxf(v, __shfl_xor_sync(0xffffffffu, v, o));
        if (lane == 0) rred[w] = v;
    }
    __syncthreads();
#pragma unroll
    for (int rr = 0; rr < RPB; rr++) {
        const float mx = rred[rr];
        float4 e;
        e.x = __expf(x4[rr].x - mx);
        e.y = __expf(x4[rr].y - mx);
        e.z = __expf(x4[rr].z - mx);
        e.w = __expf(x4[rr].w - mx);
        x4[rr] = e;
        part[rr][t] = (e.x + e.y) + (e.z + e.w);
    }
    __syncthreads();
    {
        const int w = t >> 5, lane = t & 31;
        float v = part[w][lane];
#pragma unroll
        for (int k = 1; k < 8; k++) v += part[w][lane + k * 32];
#pragma unroll
        for (int o = 16; o > 0; o >>= 1) v += __shfl_xor_sync(0xffffffffu, v, o);
        if (lane == 0) rred[w] = 1.0f / v;
    }
    __syncthreads();
    float4 cs = make_float4(0.f, 0.f, 0.f, 0.f);
#pragma unroll
    for (int rr = 0; rr < RPB; rr++) {
        const float inv = rred[rr];
        ushort4 u = enc4(x4[rr].x * inv, x4[rr].y * inv, x4[rr].z * inv, x4[rr].w * inv);
        float4 yd = dec4(u);
        float4 E;
        E.x = __expf(yd.x); E.y = __expf(yd.y); E.z = __expf(yd.z); E.w = __expf(yd.w);
        *(ushort4*)&g_Y[((size_t)b * NN + r0 + rr) * NN + j0] = u;
        cs.x += E.x; cs.y += E.y; cs.z += E.z; cs.w += E.w;
    }
    *(float4*)&g_part[((size_t)blockIdx.x * BB + b) * NN + j0] = cs;
}

// ===========================================================================
// Reduce colsum partials. grid (32, BB) = 1024 blocks, 32 cols each.
// ===========================================================================
__global__ __launch_bounds__(256) void k_reduce() {
    const int b = blockIdx.y, g = blockIdx.x, t = threadIdx.x;
    const int c = t & 7, p0 = t >> 3;
    const float4* P = (const float4*)g_part;
    float4 s = make_float4(0.f, 0.f, 0.f, 0.f);
#pragma unroll
    for (int p = p0; p < NBLK; p += 32) {
        float4 v = P[((size_t)p * BB + b) * (NN / 4) + g * 8 + c];
        s.x += v.x; s.y += v.y; s.z += v.z; s.w += v.w;
    }
    __shared__ float4 sm[32][8];
    sm[p0][c] = s;
    __syncthreads();
    if (t < 8) {
        float4 a = sm[0][t];
#pragma unroll
        for (int p = 1; p < 32; p++) {
            float4 v = sm[p][t];
            a.x += v.x; a.y += v.y; a.z += v.z; a.w += v.w;
        }
        *(float4*)&g_colsum[b * NN + g * 32 + t * 4] = a;
    }
}

// ===========================================================================
// Fused pair on uint16 y-state: col softmax + row softmax, one R+W pass.
//   E1 = exp(y); c = E1*ic; r = exp(c); y' = r*ir; store enc(y'),
//   partials = colsum of exp(dec(enc(y'))).
// ===========================================================================
__global__ __launch_bounds__(256, 4) void k_fused() {
    const int b = blockIdx.y, r0 = blockIdx.x * RPB, t = threadIdx.x;
    const int j0 = t * 4;
    __shared__ float part[RPB][256];
    __shared__ float rinv[RPB];

    float4 cv = *(const float4*)&g_colsum[b * NN + j0];
    const float4 ic = make_float4(1.0f / cv.x, 1.0f / cv.y, 1.0f / cv.z, 1.0f / cv.w);

    float4 r4[RPB];
#pragma unroll
    for (int rr = 0; rr < RPB; rr++) {
        ushort4 u = *(const ushort4*)&g_Y[((size_t)b * NN + r0 + rr) * NN + j0];
        float4 y = dec4(u);
        float4 r;
        r.x = __expf(__expf(y.x) * ic.x);
        r.y = __expf(__expf(y.y) * ic.y);
        r.z = __expf(__expf(y.z) * ic.z);
        r.w = __expf(__expf(y.w) * ic.w);
        r4[rr] = r;
        part[rr][t] = (r.x + r.y) + (r.z + r.w);
    }
    __syncthreads();
    {
        const int w = t >> 5, lane = t & 31;
        float v = part[w][lane];
#pragma unroll
        for (int k = 1; k < 8; k++) v += part[w][lane + k * 32];
#pragma unroll
        for (int o = 16; o > 0; o >>= 1) v += __shfl_xor_sync(0xffffffffu, v, o);
        if (lane == 0) rinv[w] = 1.0f / v;
    }
    __syncthreads();
    float4 cs = make_float4(0.f, 0.f, 0.f, 0.f);
#pragma unroll
    for (int rr = 0; rr < RPB; rr++) {
        const float ir = rinv[rr];
        ushort4 u = enc4(r4[rr].x * ir, r4[rr].y * ir, r4[rr].z * ir, r4[rr].w * ir);
        float4 yd = dec4(u);
        *(ushort4*)&g_Y[((size_t)b * NN + r0 + rr) * NN + j0] = u;
        cs.x += __expf(yd.x);
        cs.y += __expf(yd.y);
        cs.z += __expf(yd.z);
        cs.w += __expf(yd.w);
    }
    *(float4*)&g_part[((size_t)blockIdx.x * BB + b) * NN + j0] = cs;
}

// Last pair: col#9 + row#10; store E10 = exp(y10) as bf16 hi/lo + partials.
__global__ __launch_bounds__(256, 4) void k_fused_last() {
    const int b = blockIdx.y, r0 = blockIdx.x * RPB, t = threadIdx.x;
    const int j0 = t * 4;
    __shared__ float part[RPB][256];
    __shared__ float rinv[RPB];

    float4 cv = *(const float4*)&g_colsum[b * NN + j0];
    const float4 ic = make_float4(1.0f / cv.x, 1.0f / cv.y, 1.0f / cv.z, 1.0f / cv.w);

    float4 r4[RPB];
#pragma unroll
    for (int rr = 0; rr < RPB; rr++) {
        ushort4 u = *(const ushort4*)&g_Y[((size_t)b * NN + r0 + rr) * NN + j0];
        float4 y = dec4(u);
        float4 r;
        r.x = __expf(__expf(y.x) * ic.x);
        r.y = __expf(__expf(y.y) * ic.y);
        r.z = __expf(__expf(y.z) * ic.z);
        r.w = __expf(__expf(y.w) * ic.w);
        r4[rr] = r;
        part[rr][t] = (r.x + r.y) + (r.z + r.w);
    }
    __syncthreads();
    {
        const int w = t >> 5, lane = t & 31;
        float v = part[w][lane];
#pragma unroll
        for (int k = 1; k < 8; k++) v += part[w][lane + k * 32];
#pragma unroll
        for (int o = 16; o > 0; o >>= 1) v += __shfl_xor_sync(0xffffffffu, v, o);
        if (lane == 0) rinv[w] = 1.0f / v;
    }
    __syncthreads();
    float4 cs = make_float4(0.f, 0.f, 0.f, 0.f);
#pragma unroll
    for (int rr = 0; rr < RPB; rr++) {
        const float ir = rinv[rr];
        float Ex = __expf(r4[rr].x * ir);
        float Ey = __expf(r4[rr].y * ir);
        float Ez = __expf(r4[rr].z * ir);
        float Ew = __expf(r4[rr].w * ir);
        PackB4 H, L;
        H.h[0] = __float2bfloat16(Ex); L.h[0] = __float2bfloat16(Ex - __bfloat162float(H.h[0]));
        H.h[1] = __float2bfloat16(Ey); L.h[1] = __float2bfloat16(Ey - __bfloat162float(H.h[1]));
        H.h[2] = __float2bfloat16(Ez); L.h[2] = __float2bfloat16(Ez - __bfloat162float(H.h[2]));
        H.h[3] = __float2bfloat16(Ew); L.h[3] = __float2bfloat16(Ew - __bfloat162float(H.h[3]));
        const size_t idx = ((size_t)b * NN + r0 + rr) * NN + j0;
        *(uint2*)&g_Eh[idx] = H.u;
        *(uint2*)&g_El[idx] = L.u;
        cs.x += Ex; cs.y += Ey; cs.z += Ez; cs.w += Ew;
    }
    *(float4*)&g_part[((size_t)blockIdx.x * BB + b) * NN + j0] = cs;
}

// ===========================================================================
// B precompute: g_B[b][k][0:128]=hi, [128:256]=lo of inv_colsum[k]*feat[k][f]
// ===========================================================================
__global__ __launch_bounds__(256) void k_prepB(const float* __restrict__ feat) {
    const int b = blockIdx.y, k = blockIdx.x * 8 + (threadIdx.x >> 5);
    const int f4 = (threadIdx.x & 31) * 4;
    const float ic = 1.0f / g_colsum[b * NN + k];
    float4 v = *(const float4*)&feat[((size_t)b * NN + k) * FF + f4];
    v.x *= ic; v.y *= ic; v.z *= ic; v.w *= ic;
    PackB4 H, L;
    H.h[0] = __float2bfloat16(v.x); L.h[0] = __float2bfloat16(v.x - __bfloat162float(H.h[0]));
    H.h[1] = __float2bfloat16(v.y); L.h[1] = __float2bfloat16(v.y - __bfloat162float(H.h[1]));
    H.h[2] = __float2bfloat16(v.z); L.h[2] = __float2bfloat16(v.z - __bfloat162float(H.h[2]));
    H.h[3] = __float2bfloat16(v.w); L.h[3] = __float2bfloat16(v.w - __bfloat162float(H.h[3]));
    const size_t rb = ((size_t)b * NN + k) * 256;
    *(uint2*)&g_B[rb + f4] = H.u;
    *(uint2*)&g_B[rb + 128 + f4] = L.u;
}

// ===========================================================================
// HMMA bf16 split GEMM (unchanged from passing R9 version)
// ===========================================================================
#define ABUF 37888
#define AHI 0
#define ALO 10240
#define BHI 20480
#define BLO_OFF 8704

__global__ __launch_bounds__(256) void k_gemm(float* __restrict__ out) {
    extern __shared__ char smem[];
    const int b = blockIdx.y, i0 = blockIdx.x * 128, t = threadIdx.x;
    const int wid = t >> 5, lane = t & 31;
    const int wm = wid & 3, wn = wid >> 2;
    const uint32_t sb = smem_u32(smem);

    const int rowA = t >> 1, halfA = (t & 1) * 32;
    const int rowB = t >> 3, pB = (t & 7) * 64;
    const char* srcAh = (const char*)(g_Eh + ((size_t)b * NN + i0 + rowA) * NN) + halfA;
    const char* srcAl = (const char*)(g_El + ((size_t)b * NN + i0 + rowA) * NN) + halfA;
    const char* srcB  = (const char*)(g_B + (size_t)b * NN * 256) + rowB * 512 + pB;
    const uint32_t dAh = sb + AHI + rowA * 80 + halfA;
    const uint32_t dAl = sb + ALO + rowA * 80 + halfA;
    const uint32_t dB  = sb + BHI + (pB < 256 ? 0 : BLO_OFF) + rowB * 272 + (pB & 255);

#define ISSUE_CHUNK(cc)  do {                                            \
        const int _s = (cc) & 1;                                         \
        const size_t _ao = (size_t)(cc) * CK * 2;                        \
        CP16(dAh + _s * ABUF,      srcAh + _ao);                         \
        CP16(dAh + _s * ABUF + 16, srcAh + _ao + 16);                    \
        CP16(dAl + _s * ABUF,      srcAl + _ao);                         \
        CP16(dAl + _s * ABUF + 16, srcAl + _ao + 16);                    \
        const size_t _bo = (size_t)(cc) * CK * 512;                      \
        CP16(dB + _s * ABUF,      srcB + _bo);                           \
        CP16(dB + _s * ABUF + 16, srcB + _bo + 16);                      \
        CP16(dB + _s * ABUF + 32, srcB + _bo + 32);                      \
        CP16(dB + _s * ABUF + 48, srcB + _bo + 48);                      \
        CP_COMMIT();                                                     \
    } while (0)

    float acc[2][8][4];
#pragma unroll
    for (int mf = 0; mf < 2; mf++)
#pragma unroll
        for (int nf = 0; nf < 8; nf++)
#pragma unroll
            for (int q = 0; q < 4; q++) acc[mf][nf][q] = 0.f;

    ISSUE_CHUNK(0);

    for (int c = 0; c < GC; ++c) {
        if (c < GC - 1) { ISSUE_CHUNK(c + 1); CP_WAIT1(); }
        else            { CP_WAIT0(); }
        __syncthreads();

        const uint32_t bufA = sb + (c & 1) * ABUF;
#pragma unroll
        for (int ks = 0; ks < 2; ks++) {
            uint32_t aH[2][4], aL[2][4];
#pragma unroll
            for (int mf = 0; mf < 2; mf++) {
                const int r0 = wm * 32 + mf * 16;
                const uint32_t ad = bufA + AHI + (r0 + (lane & 15)) * 80 + ks * 32 + (lane >> 4) * 16;
                ldsm_x4(aH[mf], ad);
                ldsm_x4(aL[mf], ad + (ALO - AHI));
            }
            uint32_t bH[4][4], bL[4][4];
#pragma unroll
            for (int ng = 0; ng < 4; ng++) {
                const int n0 = wn * 64 + ng * 16;
                const uint32_t bd = bufA + BHI + (ks * 16 + (lane & 15)) * 272 + n0 * 2 + (lane >> 4) * 16;
                ldsm_x4_t(bH[ng], bd);
                ldsm_x4_t(bL[ng], bd + BLO_OFF);
            }
#pragma unroll
            for (int mf = 0; mf < 2; mf++)
#pragma unroll
                for (int ng = 0; ng < 4; ng++)
#pragma unroll
                    for (int h = 0; h < 2; h++) {
                        float* d = acc[mf][ng * 2 + h];
                        mma_bf16(d, aH[mf], &bH[ng][h * 2]);
                        mma_bf16(d, aH[mf], &bL[ng][h * 2]);
                        mma_bf16(d, aL[mf], &bH[ng][h * 2]);
                    }
        }
        __syncthreads();
    }

    const int gid = lane >> 2, t4 = lane & 3;
#pragma unroll
    for (int mf = 0; mf < 2; mf++) {
        const int row = i0 + wm * 32 + mf * 16 + gid;
#pragma unroll
        for (int nf = 0; nf < 8; nf++) {
            const int col = wn * 64 + nf * 8 + t4 * 2;
            const float* d = acc[mf][nf];
            *(float2*)&out[((size_t)b * NN + row) * FF + col]     = make_float2(d[0], d[1]);
            *(float2*)&out[((size_t)b * NN + row + 8) * FF + col] = make_float2(d[2], d[3]);
        }
    }
}

// ===========================================================================
extern "C" void kernel_launch(void* const* d_in, const int* in_sizes, int n_in,
                              void* d_out, int out_size) {
    const float* feat = (const float*)d_in[0];   // [B,N,F]
    const float* tmpl = (const float*)d_in[1];   // [1,N,N]
    const float* uni  = (const float*)d_in[2];   // [B,N,N]
    float* out = (float*)d_out;                  // [B,N,F]

    cudaFuncSetAttribute(k_gemm, cudaFuncAttributeMaxDynamicSharedMemorySize, 2 * ABUF);

    k_init<<<dim3(NBLK, BB), 256>>>(tmpl, uni);
    k_reduce<<<dim3(32, BB), 256>>>();
    for (int it = 0; it < 8; ++it) {
        k_fused<<<dim3(NBLK, BB), 256>>>();
        k_reduce<<<dim3(32, BB), 256>>>();
    }
    k_fused_last<<<dim3(NBLK, BB), 256>>>();
    k_reduce<<<dim3(32, BB), 256>>>();
    k_prepB<<<dim3(NN / 8, BB), 256>>>(feat);
    k_gemm<<<dim3(8, BB), 256, 2 * ABUF>>>(out);
}

// round 11
// speedup vs baseline: 2.3429x; 1.1980x over previous
#include <cuda_runtime.h>
#include <cuda_bf16.h>
#include <math.h>
#include <stdint.h>

#define BB 32
#define NN 1024
#define FF 128
#define RPB 8
#define NBLK (NN / RPB)
#define GC 32
#define CK 32

// State: E = exp(y) in [1, e], uint16 fixed-point: 64MB
__device__ unsigned short g_Q[BB * NN * NN];
__device__ float g_colsum[BB * NN];
__device__ float g_part[NBLK * BB * NN];          // 16MB colsum partials
__device__ __nv_bfloat16 g_Eh[BB * NN * NN];      // 64MB final E hi
__device__ __nv_bfloat16 g_El[BB * NN * NN];      // 64MB final E lo
__device__ __nv_bfloat16 g_B[BB * NN * 256];      // 16MB scaled feature [hi|lo]

// ---------------- fixed-point (magic-number, no cvt pipe) ----------------
#define EMAXR 1.7182837f                 // slightly above e-1 for range safety
#define K1C (EMAXR / 65535.0f)           // dec scale
#define C1C (1.0f - 8388608.0f * K1C)    // dec offset
#define K2C (65535.0f / EMAXR)           // enc scale
#define C2C (8388608.0f - K2C)           // enc offset: t = (E-1)*K2 + 2^23

__device__ __forceinline__ float decE(uint32_t u16) {
    return fmaf(__uint_as_float(0x4B000000u | u16), K1C, C1C);
}
__device__ __forceinline__ uint32_t enc2(float a, float b) {
    uint32_t ba = __float_as_uint(fmaf(a, K2C, C2C));
    uint32_t bb = __float_as_uint(fmaf(b, K2C, C2C));
    return (ba & 0xFFFFu) | (bb << 16);
}

// ---------------- PTX helpers (plain compute_103-safe) ----------------
__device__ __forceinline__ uint32_t smem_u32(const void* p) {
    uint32_t a;
    asm("{ .reg .u64 t; cvta.to.shared.u64 t, %1; cvt.u32.u64 %0, t; }" : "=r"(a) : "l"(p));
    return a;
}
#define CP16(dst, src) asm volatile("cp.async.cg.shared.global [%0], [%1], 16;" :: "r"(dst), "l"(src))
#define CP_COMMIT()    asm volatile("cp.async.commit_group;" ::: "memory")
#define CP_WAIT1()     asm volatile("cp.async.wait_group 1;" ::: "memory")
#define CP_WAIT0()     asm volatile("cp.async.wait_group 0;" ::: "memory")

__device__ __forceinline__ void ldsm_x4(uint32_t* r, uint32_t addr) {
    asm volatile("ldmatrix.sync.aligned.m8n8.x4.shared.b16 {%0,%1,%2,%3}, [%4];"
                 : "=r"(r[0]), "=r"(r[1]), "=r"(r[2]), "=r"(r[3]) : "r"(addr));
}
__device__ __forceinline__ void ldsm_x4_t(uint32_t* r, uint32_t addr) {
    asm volatile("ldmatrix.sync.aligned.m8n8.x4.trans.shared.b16 {%0,%1,%2,%3}, [%4];"
                 : "=r"(r[0]), "=r"(r[1]), "=r"(r[2]), "=r"(r[3]) : "r"(addr));
}
__device__ __forceinline__ void mma_bf16(float* d, const uint32_t* a, const uint32_t* b) {
    asm volatile("mma.sync.aligned.m16n8k16.row.col.f32.bf16.bf16.f32 "
                 "{%0,%1,%2,%3}, {%4,%5,%6,%7}, {%8,%9}, {%0,%1,%2,%3};"
                 : "+f"(d[0]), "+f"(d[1]), "+f"(d[2]), "+f"(d[3])
                 : "r"(a[0]), "r"(a[1]), "r"(a[2]), "r"(a[3]), "r"(b[0]), "r"(b[1]));
}

union PackB4 { __nv_bfloat16 h[4]; uint2 u; };

// ===========================================================================
// Init: m = (tmpl+gumbel)/T ; row softmax #1 ; store enc(E1=exp(y1)) + partials
// ===========================================================================
__global__ __launch_bounds__(256, 4) void k_init(const float* __restrict__ tmpl,
                                                 const float* __restrict__ uni) {
    const int b = blockIdx.y, r0 = blockIdx.x * RPB, t = threadIdx.x;
    const int j0 = t * 4;
    __shared__ float part[RPB][256];
    __shared__ float rred[RPB];

    float4 x4[RPB];
#pragma unroll
    for (int rr = 0; rr < RPB; rr++) {
        const int row = r0 + rr;
        float4 u = *(const float4*)&uni[((size_t)b * NN + row) * NN + j0];
        float4 tm = *(const float4*)&tmpl[(size_t)row * NN + j0];
        float4 x;
        x.x = (tm.x - __logf(-logf(u.x + 1e-12f) + 1e-12f)) * 5.0f;
        x.y = (tm.y - __logf(-logf(u.y + 1e-12f) + 1e-12f)) * 5.0f;
        x.z = (tm.z - __logf(-logf(u.z + 1e-12f) + 1e-12f)) * 5.0f;
        x.w = (tm.w - __logf(-logf(u.w + 1e-12f) + 1e-12f)) * 5.0f;
        x4[rr] = x;
        part[rr][t] = fmaxf(fmaxf(x.x, x.y), fmaxf(x.z, x.w));
    }
    __syncthreads();
    {
        const int w = t >> 5, lane = t & 31;
        float v = part[w][lane];
#pragma unroll
        for (int k = 1; k < 8; k++) v = fmaxf(v, part[w][lane + k * 32]);
#pragma unroll
        for (int o = 16; o > 0; o >>= 1) v = fmaxf(v, __shfl_xor_sync(0xffffffffu, v, o));
        if (lane == 0) rred[w] = v;
    }
    __syncthreads();
#pragma unroll
    for (int rr = 0; rr < RPB; rr++) {
        const float mx = rred[rr];
        float4 e;
        e.x = __expf(x4[rr].x - mx);
        e.y = __expf(x4[rr].y - mx);
        e.z = __expf(x4[rr].z - mx);
        e.w = __expf(x4[rr].w - mx);
        x4[rr] = e;
        part[rr][t] = (e.x + e.y) + (e.z + e.w);
    }
    __syncthreads();
    {
        const int w = t >> 5, lane = t & 31;
        float v = part[w][lane];
#pragma unroll
        for (int k = 1; k < 8; k++) v += part[w][lane + k * 32];
#pragma unroll
        for (int o = 16; o > 0; o >>= 1) v += __shfl_xor_sync(0xffffffffu, v, o);
        if (lane == 0) rred[w] = 1.0f / v;
    }
    __syncthreads();
    float4 cs = make_float4(0.f, 0.f, 0.f, 0.f);
#pragma unroll
    for (int rr = 0; rr < RPB; rr++) {
        const float inv = rred[rr];
        float Ex = __expf(x4[rr].x * inv);
        float Ey = __expf(x4[rr].y * inv);
        float Ez = __expf(x4[rr].z * inv);
        float Ew = __expf(x4[rr].w * inv);
        uint2 o;
        o.x = enc2(Ex, Ey);
        o.y = enc2(Ez, Ew);
        *(uint2*)&g_Q[((size_t)b * NN + r0 + rr) * NN + j0] = o;
        cs.x += Ex; cs.y += Ey; cs.z += Ez; cs.w += Ew;
    }
    *(float4*)&g_part[((size_t)blockIdx.x * BB + b) * NN + j0] = cs;
}

// ===========================================================================
// Reduce colsum partials. grid (32, BB).
// ===========================================================================
__global__ __launch_bounds__(256) void k_reduce() {
    const int b = blockIdx.y, g = blockIdx.x, t = threadIdx.x;
    const int c = t & 7, p0 = t >> 3;
    const float4* P = (const float4*)g_part;
    float4 s = make_float4(0.f, 0.f, 0.f, 0.f);
#pragma unroll
    for (int p = p0; p < NBLK; p += 32) {
        float4 v = P[((size_t)p * BB + b) * (NN / 4) + g * 8 + c];
        s.x += v.x; s.y += v.y; s.z += v.z; s.w += v.w;
    }
    __shared__ float4 sm[32][8];
    sm[p0][c] = s;
    __syncthreads();
    if (t < 8) {
        float4 a = sm[0][t];
#pragma unroll
        for (int p = 1; p < 32; p++) {
            float4 v = sm[p][t];
            a.x += v.x; a.y += v.y; a.z += v.z; a.w += v.w;
        }
        *(float4*)&g_colsum[b * NN + g * 32 + t * 4] = a;
    }
}

// ===========================================================================
// Fused pair on uint16 E-state: r = exp(E*ic); E' = exp(r*ir); store enc(E');
// partials = colsum of E'. Only 2 MUFU + 0 cvt per element.
// ===========================================================================
__global__ __launch_bounds__(256, 4) void k_fused() {
    const int b = blockIdx.y, r0 = blockIdx.x * RPB, t = threadIdx.x;
    const int j0 = t * 4;
    __shared__ float part[RPB][256];
    __shared__ float rinv[RPB];

    float4 cv = *(const float4*)&g_colsum[b * NN + j0];
    const float4 ic = make_float4(1.0f / cv.x, 1.0f / cv.y, 1.0f / cv.z, 1.0f / cv.w);

    float4 r4[RPB];
#pragma unroll
    for (int rr = 0; rr < RPB; rr++) {
        uint2 w = *(const uint2*)&g_Q[((size_t)b * NN + r0 + rr) * NN + j0];
        float4 r;
        r.x = __expf(decE(w.x & 0xFFFFu) * ic.x);
        r.y = __expf(decE(w.x >> 16) * ic.y);
        r.z = __expf(decE(w.y & 0xFFFFu) * ic.z);
        r.w = __expf(decE(w.y >> 16) * ic.w);
        r4[rr] = r;
        part[rr][t] = (r.x + r.y) + (r.z + r.w);
    }
    __syncthreads();
    {
        const int w = t >> 5, lane = t & 31;
        float v = part[w][lane];
#pragma unroll
        for (int k = 1; k < 8; k++) v += part[w][lane + k * 32];
#pragma unroll
        for (int o = 16; o > 0; o >>= 1) v += __shfl_xor_sync(0xffffffffu, v, o);
        if (lane == 0) rinv[w] = 1.0f / v;
    }
    __syncthreads();
    float4 cs = make_float4(0.f, 0.f, 0.f, 0.f);
#pragma unroll
    for (int rr = 0; rr < RPB; rr++) {
        const float ir = rinv[rr];
        float Ex = __expf(r4[rr].x * ir);
        float Ey = __expf(r4[rr].y * ir);
        float Ez = __expf(r4[rr].z * ir);
        float Ew = __expf(r4[rr].w * ir);
        uint2 o;
        o.x = enc2(Ex, Ey);
        o.y = enc2(Ez, Ew);
        *(uint2*)&g_Q[((size_t)b * NN + r0 + rr) * NN + j0] = o;
        cs.x += Ex; cs.y += Ey; cs.z += Ez; cs.w += Ew;
    }
    *(float4*)&g_part[((size_t)blockIdx.x * BB + b) * NN + j0] = cs;
}

// Last pair: col#9 + row#10; store E10 as bf16 hi/lo + partials.
__global__ __launch_bounds__(256, 4) void k_fused_last() {
    const int b = blockIdx.y, r0 = blockIdx.x * RPB, t = threadIdx.x;
    const int j0 = t * 4;
    __shared__ float part[RPB][256];
    __shared__ float rinv[RPB];

    float4 cv = *(const float4*)&g_colsum[b * NN + j0];
    const float4 ic = make_float4(1.0f / cv.x, 1.0f / cv.y, 1.0f / cv.z, 1.0f / cv.w);

    float4 r4[RPB];
#pragma unroll
    for (int rr = 0; rr < RPB; rr++) {
        uint2 w = *(const uint2*)&g_Q[((size_t)b * NN + r0 + rr) * NN + j0];
        float4 r;
        r.x = __expf(decE(w.x & 0xFFFFu) * ic.x);
        r.y = __expf(decE(w.x >> 16) * ic.y);
        r.z = __expf(decE(w.y & 0xFFFFu) * ic.z);
        r.w = __expf(decE(w.y >> 16) * ic.w);
        r4[rr] = r;
        part[rr][t] = (r.x + r.y) + (r.z + r.w);
    }
    __syncthreads();
    {
        const int w = t >> 5, lane = t & 31;
        float v = part[w][lane];
#pragma unroll
        for (int k = 1; k < 8; k++) v += part[w][lane + k * 32];
#pragma unroll
        for (int o = 16; o > 0; o >>= 1) v += __shfl_xor_sync(0xffffffffu, v, o);
        if (lane == 0) rinv[w] = 1.0f / v;
    }
    __syncthreads();
    float4 cs = make_float4(0.f, 0.f, 0.f, 0.f);
#pragma unroll
    for (int rr = 0; rr < RPB; rr++) {
        const float ir = rinv[rr];
        float Ex = __expf(r4[rr].x * ir);
        float Ey = __expf(r4[rr].y * ir);
        float Ez = __expf(r4[rr].z * ir);
        float Ew = __expf(r4[rr].w * ir);
        PackB4 H, L;
        H.h[0] = __float2bfloat16(Ex); L.h[0] = __float2bfloat16(Ex - __bfloat162float(H.h[0]));
        H.h[1] = __float2bfloat16(Ey); L.h[1] = __float2bfloat16(Ey - __bfloat162float(H.h[1]));
        H.h[2] = __float2bfloat16(Ez); L.h[2] = __float2bfloat16(Ez - __bfloat162float(H.h[2]));
        H.h[3] = __float2bfloat16(Ew); L.h[3] = __float2bfloat16(Ew - __bfloat162float(H.h[3]));
        const size_t idx = ((size_t)b * NN + r0 + rr) * NN + j0;
        *(uint2*)&g_Eh[idx] = H.u;
        *(uint2*)&g_El[idx] = L.u;
        cs.x += Ex; cs.y += Ey; cs.z += Ez; cs.w += Ew;
    }
    *(float4*)&g_part[((size_t)blockIdx.x * BB + b) * NN + j0] = cs;
}

// ===========================================================================
// B precompute WITH integrated final colsum reduce.
// grid (NN/8, BB): block reduces partials for its 8 k-rows, then builds
// g_B[b][k][0:128]=hi, [128:256]=lo of inv_colsum[k]*feat[k][f].
// ===========================================================================
__global__ __launch_bounds__(256) void k_prepB(const float* __restrict__ feat) {
    const int b = blockIdx.y, k0 = blockIdx.x * 8, t = threadIdx.x;
    __shared__ float sm[32][8];
    __shared__ float ics[8];
    {
        const int kk = t & 7, p0 = t >> 3;
        float s = 0.f;
#pragma unroll
        for (int p = p0; p < NBLK; p += 32)
            s += g_part[((size_t)p * BB + b) * NN + k0 + kk];
        sm[p0][kk] = s;
        __syncthreads();
        if (t < 8) {
            float a = 0.f;
#pragma unroll
            for (int p = 0; p < 32; p++) a += sm[p][t];
            ics[t] = 1.0f / a;
        }
        __syncthreads();
    }
    const int k = k0 + (t >> 5);
    const int f4 = (t & 31) * 4;
    const float ic = ics[t >> 5];
    float4 v = *(const float4*)&feat[((size_t)b * NN + k) * FF + f4];
    v.x *= ic; v.y *= ic; v.z *= ic; v.w *= ic;
    PackB4 H, L;
    H.h[0] = __float2bfloat16(v.x); L.h[0] = __float2bfloat16(v.x - __bfloat162float(H.h[0]));
    H.h[1] = __float2bfloat16(v.y); L.h[1] = __float2bfloat16(v.y - __bfloat162float(H.h[1]));
    H.h[2] = __float2bfloat16(v.z); L.h[2] = __float2bfloat16(v.z - __bfloat162float(H.h[2]));
    H.h[3] = __float2bfloat16(v.w); L.h[3] = __float2bfloat16(v.w - __bfloat162float(H.h[3]));
    const size_t rb = ((size_t)b * NN + k) * 256;
    *(uint2*)&g_B[rb + f4] = H.u;
    *(uint2*)&g_B[rb + 128 + f4] = L.u;
}

// ===========================================================================
// HMMA bf16 split GEMM (unchanged, passing)
// ===========================================================================
#define ABUF 37888
#define AHI 0
#define ALO 10240
#define BHI 20480
#define BLO_OFF 8704

__global__ __launch_bounds__(256) void k_gemm(float* __restrict__ out) {
    extern __shared__ char smem[];
    const int b = blockIdx.y, i0 = blockIdx.x * 128, t = threadIdx.x;
    const int wid = t >> 5, lane = t & 31;
    const int wm = wid & 3, wn = wid >> 2;
    const uint32_t sb = smem_u32(smem);

    const int rowA = t >> 1, halfA = (t & 1) * 32;
    const int rowB = t >> 3, pB = (t & 7) * 64;
    const char* srcAh = (const char*)(g_Eh + ((size_t)b * NN + i0 + rowA) * NN) + halfA;
    const char* srcAl = (const char*)(g_El + ((size_t)b * NN + i0 + rowA) * NN) + halfA;
    const char* srcB  = (const char*)(g_B + (size_t)b * NN * 256) + rowB * 512 + pB;
    const uint32_t dAh = sb + AHI + rowA * 80 + halfA;
    const uint32_t dAl = sb + ALO + rowA * 80 + halfA;
    const uint32_t dB  = sb + BHI + (pB < 256 ? 0 : BLO_OFF) + rowB * 272 + (pB & 255);

#define ISSUE_CHUNK(cc)  do {                                            \
        const int _s = (cc) & 1;                                         \
        const size_t _ao = (size_t)(cc) * CK * 2;                        \
        CP16(dAh + _s * ABUF,      srcAh + _ao);                         \
        CP16(dAh + _s * ABUF + 16, srcAh + _ao + 16);                    \
        CP16(dAl + _s * ABUF,      srcAl + _ao);                         \
        CP16(dAl + _s * ABUF + 16, srcAl + _ao + 16);                    \
        const size_t _bo = (size_t)(cc) * CK * 512;                      \
        CP16(dB + _s * ABUF,      srcB + _bo);                           \
        CP16(dB + _s * ABUF + 16, srcB + _bo + 16);                      \
        CP16(dB + _s * ABUF + 32, srcB + _bo + 32);                      \
        CP16(dB + _s * ABUF + 48, srcB + _bo + 48);                      \
        CP_COMMIT();                                                     \
    } while (0)

    float acc[2][8][4];
#pragma unroll
    for (int mf = 0; mf < 2; mf++)
#pragma unroll
        for (int nf = 0; nf < 8; nf++)
#pragma unroll
            for (int q = 0; q < 4; q++) acc[mf][nf][q] = 0.f;

    ISSUE_CHUNK(0);

    for (int c = 0; c < GC; ++c) {
        if (c < GC - 1) { ISSUE_CHUNK(c + 1); CP_WAIT1(); }
        else            { CP_WAIT0(); }
        __syncthreads();

        const uint32_t bufA = sb + (c & 1) * ABUF;
#pragma unroll
        for (int ks = 0; ks < 2; ks++) {
            uint32_t aH[2][4], aL[2][4];
#pragma unroll
            for (int mf = 0; mf < 2; mf++) {
                const int r0 = wm * 32 + mf * 16;
                const uint32_t ad = bufA + AHI + (r0 + (lane & 15)) * 80 + ks * 32 + (lane >> 4) * 16;
                ldsm_x4(aH[mf], ad);
                ldsm_x4(aL[mf], ad + (ALO - AHI));
            }
            uint32_t bH[4][4], bL[4][4];
#pragma unroll
            for (int ng = 0; ng < 4; ng++) {
                const int n0 = wn * 64 + ng * 16;
                const uint32_t bd = bufA + BHI + (ks * 16 + (lane & 15)) * 272 + n0 * 2 + (lane >> 4) * 16;
                ldsm_x4_t(bH[ng], bd);
                ldsm_x4_t(bL[ng], bd + BLO_OFF);
            }
#pragma unroll
            for (int mf = 0; mf < 2; mf++)
#pragma unroll
                for (int ng = 0; ng < 4; ng++)
#pragma unroll
                    for (int h = 0; h < 2; h++) {
                        float* d = acc[mf][ng * 2 + h];
                        mma_bf16(d, aH[mf], &bH[ng][h * 2]);
                        mma_bf16(d, aH[mf], &bL[ng][h * 2]);
                        mma_bf16(d, aL[mf], &bH[ng][h * 2]);
                    }
        }
        __syncthreads();
    }

    const int gid = lane >> 2, t4 = lane & 3;
#pragma unroll
    for (int mf = 0; mf < 2; mf++) {
        const int row = i0 + wm * 32 + mf * 16 + gid;
#pragma unroll
        for (int nf = 0; nf < 8; nf++) {
            const int col = wn * 64 + nf * 8 + t4 * 2;
            const float* d = acc[mf][nf];
            *(float2*)&out[((size_t)b * NN + row) * FF + col]     = make_float2(d[0], d[1]);
            *(float2*)&out[((size_t)b * NN + row + 8) * FF + col] = make_float2(d[2], d[3]);
        }
    }
}

// ===========================================================================
extern "C" void kernel_launch(void* const* d_in, const int* in_sizes, int n_in,
                              void* d_out, int out_size) {
    const float* feat = (const float*)d_in[0];   // [B,N,F]
    const float* tmpl = (const float*)d_in[1];   // [1,N,N]
    const float* uni  = (const float*)d_in[2];   // [B,N,N]
    float* out = (float*)d_out;                  // [B,N,F]

    cudaFuncSetAttribute(k_gemm, cudaFuncAttributeMaxDynamicSharedMemorySize, 2 * ABUF);

    k_init<<<dim3(NBLK, BB), 256>>>(tmpl, uni);
    k_reduce<<<dim3(32, BB), 256>>>();
    for (int it = 0; it < 8; ++it) {
        k_fused<<<dim3(NBLK, BB), 256>>>();
        k_reduce<<<dim3(32, BB), 256>>>();
    }
    k_fused_last<<<dim3(NBLK, BB), 256>>>();
    k_prepB<<<dim3(NN / 8, BB), 256>>>(feat);
    k_gemm<<<dim3(8, BB), 256, 2 * ABUF>>>(out);
}